// round 11
// baseline (speedup 1.0000x reference)
#include <cuda_runtime.h>

#define BATCH 16
#define CH    256
#define IH    100
#define IW    100
#define NBOX  100
#define RH    40
#define RW    40
#define NCLS  599
#define CPB   2          // channels per CTA in resize/pool kernel (known-good)
#define OUT_ELEMS (BATCH * NCLS * CH)           // 2,453,504 floats
#define OUT_F4    (OUT_ELEMS / 4)               // 613,376 float4

// Scratch (no allocations allowed)
__device__ float g_pooled[BATCH * NBOX * CH];   // [B][N][C]  (coalesced reads in k2)
__device__ int   g_start[BATCH * (NCLS + 1)];   // class -> start offset in g_list
__device__ int   g_list[BATCH * NBOX];          // box idx sorted by class (asc n within)
__device__ int   g_scls[BATCH * NBOX];          // class at each sorted position

// Quantize one box (xyxy, image coords) to the 40x40 grid. Matches
// jnp.round (half-to-even) + clip semantics of the reference.
__device__ __forceinline__ int quantize_box(float4 bb, bool& valid) {
    const float s = 40.0f / 1024.0f;            // exact in fp32
    int x1 = max((int)rintf(bb.x * s), 0);
    int y1 = max((int)rintf(bb.y * s), 0);
    int x2 = min((int)rintf(bb.z * s), RW);
    int y2 = min((int)rintf(bb.w * s), RH);
    valid = (x1 < x2) && (y1 < y2);
    x1 = min(max(x1, 0), RW);  x2 = min(max(x2, 0), RW);
    y1 = min(max(y1, 0), RH);  y2 = min(max(y2, 0), RH);
    return x1 | (y1 << 8) | (x2 << 16) | (y2 << 24);
}

// ---------------------------------------------------------------------------
// Kernel 1: per (b, 2 channels) — direct-__ldg bilinear 100->40 resize into
// smem, then direct box-sum pooling. Additionally: every CTA zero-fills its
// slice of the output (streaming stores hidden in the gather stalls), and the
// cbas==0 CTA of each batch counting-sorts boxes by class into
// g_start / g_list / g_scls (deterministic, ascending-n within each class).
// ---------------------------------------------------------------------------
__global__ __launch_bounds__(256) void resize_pool_kernel(
        const float* __restrict__ feat, const float* __restrict__ boxes,
        const int* __restrict__ gt, float* __restrict__ out) {
    __shared__ float res[CPB][RH * RW];         // 12.8 KB
    __shared__ int   s_box[NBOX];               // packed x1,y1,x2,y2 (0 if invalid)
    __shared__ float s_pool[NBOX][CPB];         // staged for float2 writes
    __shared__ int   s_cls[NBOX];               // valid ? cls : -1 (meta CTA)
    __shared__ int   s_cnt[NCLS];               // histogram -> offsets (meta CTA)
    __shared__ int   s_blk[20];

    const int blk  = blockIdx.x;                // 0 .. BATCH*CH/CPB-1
    const int b    = blk / (CH / CPB);
    const int cbas = (blk % (CH / CPB)) * CPB;
    const int tid  = threadIdx.x;
    const bool meta = (cbas == 0);              // uniform across CTA

    // --- zero-fill this CTA's slice of the output (independent stores) ---
    {
        float4 z = make_float4(0.0f, 0.0f, 0.0f, 0.0f);
        float4* o4 = (float4*)out;
        for (int i = blk * 256 + tid; i < OUT_F4; i += 2048 * 256)
            o4[i] = z;
    }

    // --- quantize this batch's boxes (threads 0..99) ---
    bool v_me = false;
    if (tid < NBOX) {
        float4 bb = __ldg((const float4*)boxes + b * NBOX + tid);
        int pk = quantize_box(bb, v_me);
        s_box[tid] = v_me ? pk : 0;             // invalid -> x1==x2==0
        if (meta) {
            int cls = __ldg(gt + b * NBOX + tid);
            s_cls[tid] = v_me ? cls : -1;
        }
    }

    // --- bilinear resize (half-pixel centers): src = 2.5*dst + 0.75 ---
    const float* __restrict__ in0 = feat + (size_t)(b * CH + cbas) * (IH * IW);
    const float* __restrict__ in1 = in0 + IH * IW;
    for (int i = tid; i < RH * RW; i += 256) {
        int oy = i / RW, ox = i % RW;
        float sy = 2.5f * (float)oy + 0.75f;    // frac is exactly .75 or .25
        float sx = 2.5f * (float)ox + 0.75f;
        int y0 = (int)sy;  float fy = sy - (float)y0;
        int x0 = (int)sx;  float fx = sx - (float)x0;
        int off = y0 * IW + x0;
        float gx0 = 1.0f - fx, gy0 = 1.0f - fy;
        float a00 = __ldg(in0 + off),      a01 = __ldg(in0 + off + 1);
        float a10 = __ldg(in0 + off + IW), a11 = __ldg(in0 + off + IW + 1);
        float b00 = __ldg(in1 + off),      b01 = __ldg(in1 + off + 1);
        float b10 = __ldg(in1 + off + IW), b11 = __ldg(in1 + off + IW + 1);
        res[0][i] = gy0 * (gx0 * a00 + fx * a01) + fy * (gx0 * a10 + fx * a11);
        res[1][i] = gy0 * (gx0 * b00 + fx * b01) + fy * (gx0 * b10 + fx * b11);
    }
    __syncthreads();

    // --- direct box-average pooling: thread = (plane, box) ---
    if (tid < NBOX * CPB) {
        int n = tid % NBOX;
        int p = tid / NBOX;
        int pk = s_box[n];
        int x1 = pk & 0xFF, y1 = (pk >> 8) & 0xFF;
        int x2 = (pk >> 16) & 0xFF, y2 = (pk >> 24) & 0xFF;
        float out_v = 0.0f;
        if (x1 < x2) {                          // valid (invalid stored as 0)
            float s = 0.0f;
            const float* r = res[p];
            for (int y = y1; y < y2; y++) {
                float rs = 0.0f;
                for (int x = x1; x < x2; x++) rs += r[y * RW + x];
                s += rs;
            }
            out_v = s / (float)((y2 - y1) * (x2 - x1));
        }
        s_pool[n][p] = out_v;
    }
    __syncthreads();

    // --- transposed write: one float2 per box into [B][N][C] ---
    if (tid < NBOX) {
        float2 v2 = make_float2(s_pool[tid][0], s_pool[tid][1]);
        *(float2*)(g_pooled + (size_t)(b * NBOX + tid) * CH + cbas) = v2;
    }

    // --- meta CTA only: counting-sort boxes by class (deterministic) ---
    if (meta) {
        for (int i = tid; i < NCLS; i += 256) s_cnt[i] = 0;
        __syncthreads();
        if (tid < NBOX && s_cls[tid] >= 0)
            atomicAdd(&s_cnt[s_cls[tid]], 1);   // histogram
        __syncthreads();
        if (tid < 19) {                          // group sums (19 x 32)
            int s = 0;
            for (int j = 0; j < 32; j++) {
                int c = tid * 32 + j;
                if (c < NCLS) s += s_cnt[c];
            }
            s_blk[tid] = s;
        }
        __syncthreads();
        if (tid == 0) {
            int r = 0;
            for (int w = 0; w < 19; w++) { int t = s_blk[w]; s_blk[w] = r; r += t; }
            s_blk[19] = r;                      // total valid boxes
        }
        __syncthreads();
        if (tid < 19) {
            int r = s_blk[tid];
            for (int j = 0; j < 32; j++) {
                int c = tid * 32 + j;
                if (c < NCLS) { int t = s_cnt[c]; s_cnt[c] = r; r += t; }  // -> offsets
            }
        }
        __syncthreads();
        for (int i = tid; i < NCLS; i += 256)
            g_start[b * (NCLS + 1) + i] = s_cnt[i];
        if (tid == 0)
            g_start[b * (NCLS + 1) + NCLS] = s_blk[19];
        // scatter: rank = #{m<n with same class} (deterministic ascending order)
        if (tid < NBOX && s_cls[tid] >= 0) {
            int c = s_cls[tid];
            int rank = 0;
            for (int m = 0; m < tid; m++) rank += (s_cls[m] == c);
            int pos = s_cnt[c] + rank;
            g_list[b * NBOX + pos] = tid;
            g_scls[b * NBOX + pos] = c;
        }
    }
}

// ---------------------------------------------------------------------------
// Kernel 2: segment-mean only. Grid (100, 16) x 64 threads; CTA k survives
// only if sorted position k is a segment head (~84 per batch). Each survivor
// sums its presorted rows (ascending n == segment_sum order) and writes one
// 1KB output row. Empty classes never touched (zeroed by kernel 1).
// ---------------------------------------------------------------------------
__global__ __launch_bounds__(64) void seg_mean_kernel(float* __restrict__ out) {
    const int k = blockIdx.x;       // sorted position 0..99
    const int b = blockIdx.y;
    const int q = threadIdx.x;      // float4 channel-quad 0..63

    const int* sb = &g_start[b * (NCLS + 1)];
    int total = __ldg(sb + NCLS);
    if (k >= total) return;
    int cls = __ldg(&g_scls[b * NBOX + k]);
    int st  = __ldg(sb + cls);
    if (k != st) return;            // not a segment head
    int en  = __ldg(sb + cls + 1);

    const float4* __restrict__ pool =
        (const float4*)(g_pooled + (size_t)b * NBOX * CH) + q;
    float4 acc = make_float4(0.0f, 0.0f, 0.0f, 0.0f);
    for (int j = st; j < en; j++) {             // ascending n within class
        int n = __ldg(&g_list[b * NBOX + j]);
        float4 v = __ldg(pool + (size_t)n * (CH / 4));
        acc.x += v.x;  acc.y += v.y;  acc.z += v.z;  acc.w += v.w;
    }
    float inv = 1.0f / (float)(en - st);
    acc.x *= inv;  acc.y *= inv;  acc.z *= inv;  acc.w *= inv;
    ((float4*)(out + (size_t)(b * NCLS + cls) * CH))[q] = acc;
}

// ---------------------------------------------------------------------------
extern "C" void kernel_launch(void* const* d_in, const int* in_sizes, int n_in,
                              void* d_out, int out_size) {
    const float* feat  = (const float*)d_in[0];   // [16,256,100,100] f32
    const float* boxes = (const float*)d_in[1];   // [16,100,4] f32
    const int*   gt    = (const int*)d_in[2];     // [16,100] i32
    float* out = (float*)d_out;                   // [16,599,256] f32

    resize_pool_kernel<<<BATCH * (CH / CPB), 256>>>(feat, boxes, gt, out);
    dim3 g2(NBOX, BATCH);
    seg_mean_kernel<<<g2, 64>>>(out);
}